// round 3
// baseline (speedup 1.0000x reference)
#include <cuda_runtime.h>
#include <cuda_fp16.h>
#include <cuda_bf16.h>
#include <mma.h>
#include <math.h>

using namespace nvcuda;

#define D_MODEL 1024
#define N_HEADS 16
#define HDIM    64
#define SEQ     2048
#define BATCH   2
#define TOKENS  (BATCH * SEQ)      // 4096
#define QKV_N   (3 * D_MODEL)      // 3072

// Scratch (device globals: allocation-free rule)
__device__ int    g_dtype;                       // 0=f32, 1=f16, 2=bf16
__device__ __half g_xh[TOKENS * D_MODEL];        // x converted to fp16
__device__ __half g_owh[D_MODEL * D_MODEL];      // ow converted to fp16
__device__ __half g_wqkv[D_MODEL * QKV_N];       // packed qkv weights, fp16
__device__ __half g_qkv[TOKENS * QKV_N];         // [4096 x 3072] Q|K|V
__device__ __half g_merged[TOKENS * D_MODEL];    // attention output, fp16

template <typename T> __device__ __forceinline__ T cvt_out(float x);
template <> __device__ __forceinline__ float  cvt_out<float>(float x)  { return x; }
template <> __device__ __forceinline__ __half cvt_out<__half>(float x) { return __float2half(x); }

__device__ __forceinline__ float load_as(const void* p, size_t i, int dt) {
    if (dt == 0) return ((const float*)p)[i];
    if (dt == 1) return __half2float(((const __half*)p)[i]);
    return __bfloat162float(((const __nv_bfloat16*)p)[i]);
}

// ---------------------------------------------------------------------------
// Detect input dtype from x statistics. x ~ N(0,1) fp16-rounded, so the true
// interpretation has mean|x| ~= 0.798; wrong bit reinterpretations land orders
// of magnitude away. One block, deterministic.
// ---------------------------------------------------------------------------
__global__ void detect_dtype_kernel(const void* __restrict__ x) {
    __shared__ float red[3][256];
    int tid = threadIdx.x;
    float acc[3] = {0.f, 0.f, 0.f};
    for (int i = tid; i < 8192; i += 256) {
#pragma unroll
        for (int d = 0; d < 3; d++) {
            float v = fabsf(load_as(x, i, d));
            if (!isfinite(v)) v = 1e6f;
            acc[d] += fminf(v, 1e6f);
        }
    }
#pragma unroll
    for (int d = 0; d < 3; d++) red[d][tid] = acc[d];
    __syncthreads();
    for (int s = 128; s > 0; s >>= 1) {
        if (tid < s)
#pragma unroll
            for (int d = 0; d < 3; d++) red[d][tid] += red[d][tid + s];
        __syncthreads();
    }
    if (tid == 0) {
        int best = 0;
        float bestscore = 1e30f;
        for (int d = 0; d < 3; d++) {
            float mean = red[d][0] / 8192.0f;
            float score = fabsf(logf(mean + 1e-30f) - logf(0.798f));
            if (score < bestscore) { bestscore = score; best = d; }
        }
        g_dtype = best;
    }
}

// ---------------------------------------------------------------------------
// Convert any-dtype input buffer -> fp16
// ---------------------------------------------------------------------------
__global__ void convert_kernel(const void* __restrict__ src,
                               __half* __restrict__ dst, int n) {
    int i = blockIdx.x * blockDim.x + threadIdx.x;
    if (i >= n) return;
    dst[i] = __float2half(load_as(src, i, g_dtype));
}

// ---------------------------------------------------------------------------
// Convert + pack qw|kw|vw into one fp16 [K=1024, N=3072] weight
// ---------------------------------------------------------------------------
__global__ void pack_qkv_kernel(const void* __restrict__ qw,
                                const void* __restrict__ kw,
                                const void* __restrict__ vw,
                                __half* __restrict__ wp) {
    int i = blockIdx.x * blockDim.x + threadIdx.x;
    if (i >= D_MODEL * D_MODEL) return;
    int k = i >> 10;          // row 0..1023
    int c = i & 1023;         // col 0..1023
    int dt = g_dtype;
    __half* dst = wp + (size_t)k * QKV_N + c;
    dst[0]            = __float2half(load_as(qw, i, dt));
    dst[D_MODEL]      = __float2half(load_as(kw, i, dt));
    dst[2 * D_MODEL]  = __float2half(load_as(vw, i, dt));
}

// ---------------------------------------------------------------------------
// wmma GEMM: C[MxN] = A[MxK] (fp16, ld=K) * B[KxN] (fp16, ld=N), fp32 accum.
// Block tile 128x128, BK=32, 8 warps (4 along M x 2 along N), warp tile 32x64.
// ---------------------------------------------------------------------------
template <typename OutT>
__global__ __launch_bounds__(256)
void gemm_f16_kernel(const __half* __restrict__ A,
                     const __half* __restrict__ B,
                     OutT* __restrict__ C,
                     int M, int N, int K) {
    constexpr int BM = 128, BN = 128, BK = 32;
    __shared__ __half sA[BM][BK + 8];
    __shared__ __half sB[BK][BN + 8];
    __shared__ float  sScr[8][256];

    int tid  = threadIdx.x;
    int warp = tid >> 5, lane = tid & 31;
    int wm = warp & 3;
    int wn = warp >> 2;
    int bm = blockIdx.y * BM;
    int bn = blockIdx.x * BN;

    wmma::fragment<wmma::accumulator, 16, 16, 16, float> acc[2][4];
#pragma unroll
    for (int i = 0; i < 2; i++)
#pragma unroll
        for (int j = 0; j < 4; j++) wmma::fill_fragment(acc[i][j], 0.0f);

    for (int k0 = 0; k0 < K; k0 += BK) {
        for (int i = tid; i < (BM * BK) / 8; i += 256) {
            int r = i >> 2, cg = i & 3;
            *(uint4*)&sA[r][cg * 8] =
                *(const uint4*)&A[(size_t)(bm + r) * K + k0 + cg * 8];
        }
        for (int i = tid; i < (BK * BN) / 8; i += 256) {
            int r = i >> 4, cg = i & 15;
            *(uint4*)&sB[r][cg * 8] =
                *(const uint4*)&B[(size_t)(k0 + r) * N + bn + cg * 8];
        }
        __syncthreads();
#pragma unroll
        for (int kk = 0; kk < BK; kk += 16) {
            wmma::fragment<wmma::matrix_a, 16, 16, 16, half, wmma::row_major> af[2];
            wmma::fragment<wmma::matrix_b, 16, 16, 16, half, wmma::row_major> bf[4];
#pragma unroll
            for (int i = 0; i < 2; i++)
                wmma::load_matrix_sync(af[i], &sA[wm * 32 + i * 16][kk], BK + 8);
#pragma unroll
            for (int j = 0; j < 4; j++)
                wmma::load_matrix_sync(bf[j], &sB[kk][wn * 64 + j * 16], BN + 8);
#pragma unroll
            for (int i = 0; i < 2; i++)
#pragma unroll
                for (int j = 0; j < 4; j++)
                    wmma::mma_sync(acc[i][j], af[i], bf[j], acc[i][j]);
        }
        __syncthreads();
    }

#pragma unroll
    for (int i = 0; i < 2; i++) {
#pragma unroll
        for (int j = 0; j < 4; j++) {
            wmma::store_matrix_sync(&sScr[warp][0], acc[i][j], 16, wmma::mem_row_major);
            __syncwarp();
            int r0 = bm + wm * 32 + i * 16;
            int c0 = bn + wn * 64 + j * 16;
#pragma unroll
            for (int e = lane; e < 256; e += 32) {
                C[(size_t)(r0 + (e >> 4)) * N + c0 + (e & 15)] =
                    cvt_out<OutT>(sScr[warp][e]);
            }
            __syncwarp();
        }
    }
}

// ---------------------------------------------------------------------------
// RoPE in place on Q and K slices of g_qkv. Folds 1/32 score scale into Q.
// ---------------------------------------------------------------------------
__global__ void rope_kernel(__half* __restrict__ qkv) {
    int idx = blockIdx.x * blockDim.x + threadIdx.x;
    const int total = TOKENS * N_HEADS * (HDIM / 2);
    if (idx >= total) return;
    int i = idx & 31;
    int h = (idx >> 5) & 15;
    int t = idx >> 9;
    int s = t & (SEQ - 1);

    float inv = powf(10000.0f, -(float)i * (1.0f / 32.0f));
    float ang = (float)s * inv;
    float sn, cs;
    sincosf(ang, &sn, &cs);

    size_t base = (size_t)t * QKV_N + h * HDIM + 2 * i;
    float x1 = __half2float(qkv[base]);
    float x2 = __half2float(qkv[base + 1]);
    qkv[base]     = __float2half((x1 * cs - x2 * sn) * 0.03125f);
    qkv[base + 1] = __float2half((x1 * sn + x2 * cs) * 0.03125f);
    base += D_MODEL;
    x1 = __half2float(qkv[base]);
    x2 = __half2float(qkv[base + 1]);
    qkv[base]     = __float2half(x1 * cs - x2 * sn);
    qkv[base + 1] = __float2half(x1 * sn + x2 * cs);
}

// ---------------------------------------------------------------------------
// Flash attention — fp32 CUDA-core math (diagnostic/baseline).
// Block = (batch,head) x 64-query tile. 256 threads = 64 rows x 4 quarter-dims.
// ---------------------------------------------------------------------------
__global__ __launch_bounds__(256)
void attn_kernel(const __half* __restrict__ qkv, __half* __restrict__ merged) {
    extern __shared__ float smem[];
    float* sK = smem;                 // [64][68]
    float* sV = sK + 64 * 68;         // [64][68]
    float* sP = sV + 64 * 68;         // [64][68] raw scores

    int qt = blockIdx.x;
    int bh = blockIdx.y;
    int b = bh >> 4, h = bh & 15;
    const __half* Qg = qkv + (size_t)b * SEQ * QKV_N + h * HDIM;
    const __half* Kg = Qg + D_MODEL;
    const __half* Vg = Qg + 2 * D_MODEL;

    int tid  = threadIdx.x;
    int r    = tid >> 2;
    int tq   = tid & 3;
    int qrow = qt * 64 + r;

    float q[16], o[16];
    const __half* qp = Qg + (size_t)qrow * QKV_N + tq * 16;
#pragma unroll
    for (int d = 0; d < 16; d++) { q[d] = __half2float(qp[d]); o[d] = 0.0f; }
    float mrun = -1e30f, lrun = 0.0f;

    for (int kv = 0; kv <= qt; kv++) {
        __syncthreads();
        for (int i = tid; i < 4096; i += 256) {
            int rr = i >> 6, cc = i & 63;
            sK[rr * 68 + cc] = __half2float(Kg[(size_t)(kv * 64 + rr) * QKV_N + cc]);
            sV[rr * 68 + cc] = __half2float(Vg[(size_t)(kv * 64 + rr) * QKV_N + cc]);
        }
        __syncthreads();

        float tmax = -1e30f;
        for (int c = 0; c < 64; c++) {
            const float4* kp = (const float4*)&sK[c * 68 + tq * 16];
            float4 k0 = kp[0], k1 = kp[1], k2 = kp[2], k3 = kp[3];
            float s = q[0] * k0.x + q[1] * k0.y + q[2] * k0.z + q[3] * k0.w
                    + q[4] * k1.x + q[5] * k1.y + q[6] * k1.z + q[7] * k1.w
                    + q[8] * k2.x + q[9] * k2.y + q[10] * k2.z + q[11] * k2.w
                    + q[12] * k3.x + q[13] * k3.y + q[14] * k3.z + q[15] * k3.w;
            s += __shfl_xor_sync(0xffffffffu, s, 1);
            s += __shfl_xor_sync(0xffffffffu, s, 2);
            s = (kv * 64 + c <= qrow) ? s : -1e30f;
            if (tq == 0) sP[r * 68 + c] = s;
            tmax = fmaxf(tmax, s);
        }
        float mnew = fmaxf(mrun, tmax);
        float corr = __expf(mrun - mnew);
        mrun = mnew;
        lrun *= corr;
#pragma unroll
        for (int d = 0; d < 16; d++) o[d] *= corr;
        __syncwarp();

        for (int c = 0; c < 64; c++) {
            float p = __expf(sP[r * 68 + c] - mnew);
            lrun += p;
            const float4* vp = (const float4*)&sV[c * 68 + tq * 16];
            float4 v0 = vp[0], v1 = vp[1], v2 = vp[2], v3 = vp[3];
            o[0]  += p * v0.x;  o[1]  += p * v0.y;  o[2]  += p * v0.z;  o[3]  += p * v0.w;
            o[4]  += p * v1.x;  o[5]  += p * v1.y;  o[6]  += p * v1.z;  o[7]  += p * v1.w;
            o[8]  += p * v2.x;  o[9]  += p * v2.y;  o[10] += p * v2.z;  o[11] += p * v2.w;
            o[12] += p * v3.x;  o[13] += p * v3.y;  o[14] += p * v3.z;  o[15] += p * v3.w;
        }
    }

    float invl = 1.0f / lrun;
    __half* op = merged + (size_t)(b * SEQ + qrow) * D_MODEL + h * HDIM + tq * 16;
#pragma unroll
    for (int d = 0; d < 16; d++) op[d] = __float2half(o[d] * invl);
}

// ---------------------------------------------------------------------------
// Launch
// ---------------------------------------------------------------------------
extern "C" void kernel_launch(void* const* d_in, const int* in_sizes, int n_in,
                              void* d_out, int out_size) {
    const void* x  = d_in[0];
    const void* qw = d_in[1];
    const void* kw = d_in[2];
    const void* vw = d_in[3];
    const void* ow = d_in[4];
    float* out = (float*)d_out;

    __half *xh, *owh, *wqkv, *qkvb, *mg;
    cudaGetSymbolAddress((void**)&xh,   g_xh);
    cudaGetSymbolAddress((void**)&owh,  g_owh);
    cudaGetSymbolAddress((void**)&wqkv, g_wqkv);
    cudaGetSymbolAddress((void**)&qkvb, g_qkv);
    cudaGetSymbolAddress((void**)&mg,   g_merged);

    // 0. detect input dtype (f32/f16/bf16) from x statistics
    detect_dtype_kernel<<<1, 256>>>(x);

    // 1. convert inputs to fp16 + pack qkv weights
    int nx = TOKENS * D_MODEL;
    int nw = D_MODEL * D_MODEL;
    convert_kernel<<<(nx + 255) / 256, 256>>>(x, xh, nx);
    convert_kernel<<<(nw + 255) / 256, 256>>>(ow, owh, nw);
    pack_qkv_kernel<<<(nw + 255) / 256, 256>>>(qw, kw, vw, wqkv);

    // 2. QKV projection: [4096x1024] @ [1024x3072]
    dim3 g1(QKV_N / 128, TOKENS / 128);
    gemm_f16_kernel<__half><<<g1, 256>>>(xh, wqkv, qkvb, TOKENS, QKV_N, D_MODEL);

    // 3. RoPE (in place on Q,K)
    int rope_total = TOKENS * N_HEADS * (HDIM / 2);
    rope_kernel<<<(rope_total + 255) / 256, 256>>>(qkvb);

    // 4. causal flash attention
    int attn_smem = 3 * 64 * 68 * (int)sizeof(float);   // 52224
    cudaFuncSetAttribute(attn_kernel,
                         cudaFuncAttributeMaxDynamicSharedMemorySize, attn_smem);
    dim3 g2(SEQ / 64, BATCH * N_HEADS);
    attn_kernel<<<g2, 256, attn_smem>>>(qkvb, mg);

    // 5. output projection: [4096x1024] @ [1024x1024] -> fp32
    dim3 g3(D_MODEL / 128, TOKENS / 128);
    gemm_f16_kernel<float><<<g3, 256>>>(mg, owh, out, TOKENS, D_MODEL, D_MODEL);
}

// round 5
// speedup vs baseline: 4.5372x; 4.5372x over previous
#include <cuda_runtime.h>
#include <cuda_fp16.h>
#include <cuda_bf16.h>
#include <mma.h>
#include <math.h>
#include <cstdint>

using namespace nvcuda;

#define D_MODEL 1024
#define N_HEADS 16
#define HDIM    64
#define SEQ     2048
#define BATCH   2
#define TOKENS  (BATCH * SEQ)      // 4096
#define QKV_N   (3 * D_MODEL)      // 3072

// Scratch (device globals: allocation-free rule)
__device__ int    g_dtype;                       // 0=f32, 1=f16, 2=bf16
__device__ __half g_xh[TOKENS * D_MODEL];
__device__ __half g_owh[D_MODEL * D_MODEL];
__device__ __half g_wqkv[D_MODEL * QKV_N];
__device__ __half g_qkv[TOKENS * QKV_N];
__device__ __half g_merged[TOKENS * D_MODEL];

template <typename T> __device__ __forceinline__ T cvt_out(float x);
template <> __device__ __forceinline__ float  cvt_out<float>(float x)  { return x; }
template <> __device__ __forceinline__ __half cvt_out<__half>(float x) { return __float2half(x); }

__device__ __forceinline__ float load_as(const void* p, size_t i, int dt) {
    if (dt == 0) return ((const float*)p)[i];
    if (dt == 1) return __half2float(((const __half*)p)[i]);
    return __bfloat162float(((const __nv_bfloat16*)p)[i]);
}

// cp.async helpers (LDGSTS)
__device__ __forceinline__ void cp_async16(void* sptr, const void* gptr) {
    unsigned int sa = (unsigned int)__cvta_generic_to_shared(sptr);
    asm volatile("cp.async.cg.shared.global [%0], [%1], 16;\n" :: "r"(sa), "l"(gptr));
}
__device__ __forceinline__ void cp_commit() {
    asm volatile("cp.async.commit_group;\n" ::);
}
template <int N> __device__ __forceinline__ void cp_wait() {
    asm volatile("cp.async.wait_group %0;\n" :: "n"(N));
}

// ---------------------------------------------------------------------------
// Detect input dtype from x statistics (mean|x| ~= 0.798 for the true one).
// ---------------------------------------------------------------------------
__global__ void detect_dtype_kernel(const void* __restrict__ x) {
    __shared__ float red[3][256];
    int tid = threadIdx.x;
    float acc[3] = {0.f, 0.f, 0.f};
    for (int i = tid; i < 8192; i += 256) {
#pragma unroll
        for (int d = 0; d < 3; d++) {
            float v = fabsf(load_as(x, i, d));
            if (!isfinite(v)) v = 1e6f;
            acc[d] += fminf(v, 1e6f);
        }
    }
#pragma unroll
    for (int d = 0; d < 3; d++) red[d][tid] = acc[d];
    __syncthreads();
    for (int s = 128; s > 0; s >>= 1) {
        if (tid < s)
#pragma unroll
            for (int d = 0; d < 3; d++) red[d][tid] += red[d][tid + s];
        __syncthreads();
    }
    if (tid == 0) {
        int best = 0;
        float bestscore = 1e30f;
        for (int d = 0; d < 3; d++) {
            float mean = red[d][0] / 8192.0f;
            float score = fabsf(logf(mean + 1e-30f) - logf(0.798f));
            if (score < bestscore) { bestscore = score; best = d; }
        }
        g_dtype = best;
    }
}

__global__ void convert_kernel(const void* __restrict__ src,
                               __half* __restrict__ dst, int n) {
    int i = blockIdx.x * blockDim.x + threadIdx.x;
    if (i >= n) return;
    dst[i] = __float2half(load_as(src, i, g_dtype));
}

__global__ void pack_qkv_kernel(const void* __restrict__ qw,
                                const void* __restrict__ kw,
                                const void* __restrict__ vw,
                                __half* __restrict__ wp) {
    int i = blockIdx.x * blockDim.x + threadIdx.x;
    if (i >= D_MODEL * D_MODEL) return;
    int k = i >> 10;
    int c = i & 1023;
    int dt = g_dtype;
    __half* dst = wp + (size_t)k * QKV_N + c;
    dst[0]           = __float2half(load_as(qw, i, dt));
    dst[D_MODEL]     = __float2half(load_as(kw, i, dt));
    dst[2 * D_MODEL] = __float2half(load_as(vw, i, dt));
}

// ---------------------------------------------------------------------------
// wmma GEMM with 2-stage cp.async double buffering.
// C[MxN] = A[MxK] * B[KxN], fp16 in, fp32 accum. Tile 128x128x32, 8 warps.
// ---------------------------------------------------------------------------
template <typename OutT>
__global__ __launch_bounds__(256)
void gemm_f16_kernel(const __half* __restrict__ A,
                     const __half* __restrict__ B,
                     OutT* __restrict__ C,
                     int M, int N, int K) {
    constexpr int BM = 128, BN = 128, BK = 32;
    __shared__ __half sA[2][BM][BK + 8];   // 80B rows
    __shared__ __half sB[2][BK][BN + 8];   // 272B rows
    __shared__ float  sScr[8][256];

    int tid  = threadIdx.x;
    int warp = tid >> 5, lane = tid & 31;
    int wm = warp & 3;
    int wn = warp >> 2;
    int bm = blockIdx.y * BM;
    int bn = blockIdx.x * BN;
    int ntiles = K / BK;

    // per-thread fixed load slots: A: 2 uint4, B: 2 uint4
    int ar0 = tid >> 1, ac0 = (tid & 1) * 2;            // rows 0..127, col-group 0/2
    int br0 = tid >> 3, bc0 = (tid & 7) * 2;            // rows 0..31,  col-group 0..14

    auto issue_tile = [&](int k0, int st) {
#pragma unroll
        for (int u = 0; u < 2; u++)
            cp_async16(&sA[st][ar0][(ac0 + u) * 8],
                       &A[(size_t)(bm + ar0) * K + k0 + (ac0 + u) * 8]);
#pragma unroll
        for (int u = 0; u < 2; u++)
            cp_async16(&sB[st][br0][(bc0 + u) * 8],
                       &B[(size_t)(k0 + br0) * N + bn + (bc0 + u) * 8]);
        cp_commit();
    };

    wmma::fragment<wmma::accumulator, 16, 16, 16, float> acc[2][4];
#pragma unroll
    for (int i = 0; i < 2; i++)
#pragma unroll
        for (int j = 0; j < 4; j++) wmma::fill_fragment(acc[i][j], 0.0f);

    issue_tile(0, 0);

    for (int t = 0; t < ntiles; t++) {
        int cur = t & 1;
        if (t + 1 < ntiles) {
            issue_tile((t + 1) * BK, (t + 1) & 1);
            cp_wait<1>();
        } else {
            cp_wait<0>();
        }
        __syncthreads();

#pragma unroll
        for (int kk = 0; kk < BK; kk += 16) {
            wmma::fragment<wmma::matrix_a, 16, 16, 16, half, wmma::row_major> af[2];
            wmma::fragment<wmma::matrix_b, 16, 16, 16, half, wmma::row_major> bf[4];
#pragma unroll
            for (int i = 0; i < 2; i++)
                wmma::load_matrix_sync(af[i], &sA[cur][wm * 32 + i * 16][kk], BK + 8);
#pragma unroll
            for (int j = 0; j < 4; j++)
                wmma::load_matrix_sync(bf[j], &sB[cur][kk][wn * 64 + j * 16], BN + 8);
#pragma unroll
            for (int i = 0; i < 2; i++)
#pragma unroll
                for (int j = 0; j < 4; j++)
                    wmma::mma_sync(acc[i][j], af[i], bf[j], acc[i][j]);
        }
        __syncthreads();   // all reads of 'cur' done before it is refilled (t+2)
    }

#pragma unroll
    for (int i = 0; i < 2; i++) {
#pragma unroll
        for (int j = 0; j < 4; j++) {
            wmma::store_matrix_sync(&sScr[warp][0], acc[i][j], 16, wmma::mem_row_major);
            __syncwarp();
            int r0 = bm + wm * 32 + i * 16;
            int c0 = bn + wn * 64 + j * 16;
#pragma unroll
            for (int e = lane; e < 256; e += 32) {
                C[(size_t)(r0 + (e >> 4)) * N + c0 + (e & 15)] =
                    cvt_out<OutT>(sScr[warp][e]);
            }
            __syncwarp();
        }
    }
}

// ---------------------------------------------------------------------------
// RoPE in place on Q and K slices of g_qkv. Folds 1/32 score scale into Q.
// ---------------------------------------------------------------------------
__global__ void rope_kernel(__half* __restrict__ qkv) {
    int idx = blockIdx.x * blockDim.x + threadIdx.x;
    const int total = TOKENS * N_HEADS * (HDIM / 2);
    if (idx >= total) return;
    int i = idx & 31;
    int h = (idx >> 5) & 15;
    int t = idx >> 9;
    int s = t & (SEQ - 1);

    float inv = powf(10000.0f, -(float)i * (1.0f / 32.0f));
    float ang = (float)s * inv;
    float sn, cs;
    sincosf(ang, &sn, &cs);

    size_t base = (size_t)t * QKV_N + h * HDIM + 2 * i;
    float x1 = __half2float(qkv[base]);
    float x2 = __half2float(qkv[base + 1]);
    qkv[base]     = __float2half((x1 * cs - x2 * sn) * 0.03125f);
    qkv[base + 1] = __float2half((x1 * sn + x2 * cs) * 0.03125f);
    base += D_MODEL;
    x1 = __half2float(qkv[base]);
    x2 = __half2float(qkv[base + 1]);
    qkv[base]     = __float2half(x1 * cs - x2 * sn);
    qkv[base + 1] = __float2half(x1 * sn + x2 * cs);
}

// ---------------------------------------------------------------------------
// Flash attention on tensor cores. Block = (batch,head) x 64-query tile,
// 128 threads (4 warps). wmma QK^T -> fp32 S in smem -> per-row online
// softmax -> fp16 P -> wmma P@V -> rescale-accumulate O in smem.
// ---------------------------------------------------------------------------
__global__ __launch_bounds__(128)
void attn_kernel(const __half* __restrict__ qkv, __half* __restrict__ merged) {
    extern __shared__ __align__(16) char smem_raw[];
    __half* sQP = (__half*)smem_raw;          // 64x72: Q, then reused as P
    __half* sK  = sQP + 64 * 72;
    __half* sV  = sK  + 64 * 72;
    float*  sS  = (float*)(sV + 64 * 72);     // 64x72: S, then Otmp
    float*  sO  = sS + 64 * 72;
    float*  m     = sO + 64 * 72;
    float*  l     = m + 64;
    float*  alpha = l + 64;

    int qt = blockIdx.x;
    int bh = blockIdx.y;
    int b = bh >> 4, h = bh & 15;
    const __half* Qg = qkv + (size_t)b * SEQ * QKV_N + h * HDIM;
    const __half* Kg = Qg + D_MODEL;
    const __half* Vg = Qg + 2 * D_MODEL;
    int tid = threadIdx.x, warp = tid >> 5;

    for (int i = tid; i < 512; i += 128) {
        int r = i >> 3, cg = i & 7;
        *(uint4*)&sQP[r * 72 + cg * 8] =
            *(const uint4*)&Qg[(size_t)(qt * 64 + r) * QKV_N + cg * 8];
    }
    for (int i = tid; i < 64 * 72; i += 128) sO[i] = 0.0f;
    if (tid < 64) { m[tid] = -1e30f; l[tid] = 0.0f; }
    __syncthreads();

    // Q fragments persist in registers; sQP is then reused as the P buffer
    wmma::fragment<wmma::matrix_a, 16, 16, 16, half, wmma::row_major> qf[4];
#pragma unroll
    for (int kk = 0; kk < 4; kk++)
        wmma::load_matrix_sync(qf[kk], &sQP[(warp * 16) * 72 + kk * 16], 72);
    __syncthreads();

    for (int kv = 0; kv <= qt; kv++) {
        for (int i = tid; i < 512; i += 128) {
            int r = i >> 3, cg = i & 7;
            *(uint4*)&sK[r * 72 + cg * 8] =
                *(const uint4*)&Kg[(size_t)(kv * 64 + r) * QKV_N + cg * 8];
            *(uint4*)&sV[r * 72 + cg * 8] =
                *(const uint4*)&Vg[(size_t)(kv * 64 + r) * QKV_N + cg * 8];
        }
        __syncthreads();

        // S = Q @ K^T
        wmma::fragment<wmma::accumulator, 16, 16, 16, float> sacc[4];
#pragma unroll
        for (int n = 0; n < 4; n++) wmma::fill_fragment(sacc[n], 0.0f);
#pragma unroll
        for (int kk = 0; kk < 4; kk++) {
#pragma unroll
            for (int n = 0; n < 4; n++) {
                wmma::fragment<wmma::matrix_b, 16, 16, 16, half, wmma::col_major> kf;
                wmma::load_matrix_sync(kf, &sK[(n * 16) * 72 + kk * 16], 72);
                wmma::mma_sync(sacc[n], qf[kk], kf, sacc[n]);
            }
        }
#pragma unroll
        for (int n = 0; n < 4; n++)
            wmma::store_matrix_sync(&sS[(warp * 16) * 72 + n * 16], sacc[n],
                                    72, wmma::mem_row_major);
        __syncthreads();

        // online softmax, one thread per query row
        if (tid < 64) {
            int r = tid;
            int lim = (kv == qt) ? (r + 1) : 64;
            float mo = m[r];
            float mx = mo;
            for (int c = 0; c < lim; c++) mx = fmaxf(mx, sS[r * 72 + c]);
            float a = __expf(mo - mx);
            float sum = 0.0f;
            for (int c = 0; c < lim; c++) {
                float p = __expf(sS[r * 72 + c] - mx);
                sum += p;
                sQP[r * 72 + c] = __float2half(p);
            }
            for (int c = lim; c < 64; c++) sQP[r * 72 + c] = __float2half(0.0f);
            m[r] = mx;
            l[r] = l[r] * a + sum;
            alpha[r] = a;
        }
        __syncthreads();

        // Otmp = P @ V
        wmma::fragment<wmma::accumulator, 16, 16, 16, float> oacc[4];
#pragma unroll
        for (int n = 0; n < 4; n++) wmma::fill_fragment(oacc[n], 0.0f);
#pragma unroll
        for (int kk = 0; kk < 4; kk++) {
            wmma::fragment<wmma::matrix_a, 16, 16, 16, half, wmma::row_major> pf;
            wmma::load_matrix_sync(pf, &sQP[(warp * 16) * 72 + kk * 16], 72);
#pragma unroll
            for (int n = 0; n < 4; n++) {
                wmma::fragment<wmma::matrix_b, 16, 16, 16, half, wmma::row_major> vf;
                wmma::load_matrix_sync(vf, &sV[(kk * 16) * 72 + n * 16], 72);
                wmma::mma_sync(oacc[n], pf, vf, oacc[n]);
            }
        }
#pragma unroll
        for (int n = 0; n < 4; n++)
            wmma::store_matrix_sync(&sS[(warp * 16) * 72 + n * 16], oacc[n],
                                    72, wmma::mem_row_major);
        __syncthreads();

        for (int i = tid; i < 64 * 64; i += 128) {
            int r = i >> 6, c = i & 63;
            sO[r * 72 + c] = sO[r * 72 + c] * alpha[r] + sS[r * 72 + c];
        }
        __syncthreads();
    }

    for (int i = tid; i < 64 * 64; i += 128) {
        int r = i >> 6, c = i & 63;
        merged[(size_t)(b * SEQ + qt * 64 + r) * D_MODEL + h * HDIM + c] =
            __float2half(sO[r * 72 + c] / l[r]);
    }
}

// ---------------------------------------------------------------------------
// Launch
// ---------------------------------------------------------------------------
extern "C" void kernel_launch(void* const* d_in, const int* in_sizes, int n_in,
                              void* d_out, int out_size) {
    const void* x  = d_in[0];
    const void* qw = d_in[1];
    const void* kw = d_in[2];
    const void* vw = d_in[3];
    const void* ow = d_in[4];
    float* out = (float*)d_out;

    __half *xh, *owh, *wqkv, *qkvb, *mg;
    cudaGetSymbolAddress((void**)&xh,   g_xh);
    cudaGetSymbolAddress((void**)&owh,  g_owh);
    cudaGetSymbolAddress((void**)&wqkv, g_wqkv);
    cudaGetSymbolAddress((void**)&qkvb, g_qkv);
    cudaGetSymbolAddress((void**)&mg,   g_merged);

    detect_dtype_kernel<<<1, 256>>>(x);

    int nx = TOKENS * D_MODEL;
    int nw = D_MODEL * D_MODEL;
    convert_kernel<<<(nx + 255) / 256, 256>>>(x, xh, nx);
    convert_kernel<<<(nw + 255) / 256, 256>>>(ow, owh, nw);
    pack_qkv_kernel<<<(nw + 255) / 256, 256>>>(qw, kw, vw, wqkv);

    dim3 g1(QKV_N / 128, TOKENS / 128);
    gemm_f16_kernel<__half><<<g1, 256>>>(xh, wqkv, qkvb, TOKENS, QKV_N, D_MODEL);

    int rope_total = TOKENS * N_HEADS * (HDIM / 2);
    rope_kernel<<<(rope_total + 255) / 256, 256>>>(qkvb);

    int attn_smem = (3 * 64 * 72) * 2 + (2 * 64 * 72) * 4 + 3 * 64 * 4;  // 65280
    cudaFuncSetAttribute(attn_kernel,
                         cudaFuncAttributeMaxDynamicSharedMemorySize, attn_smem);
    dim3 g2(SEQ / 64, BATCH * N_HEADS);
    attn_kernel<<<g2, 128, attn_smem>>>(qkvb, mg);

    dim3 g3(D_MODEL / 128, TOKENS / 128);
    gemm_f16_kernel<float><<<g3, 256>>>(mg, owh, out, TOKENS, D_MODEL, D_MODEL);
}

// round 6
// speedup vs baseline: 5.0955x; 1.1231x over previous
#include <cuda_runtime.h>
#include <cuda_fp16.h>
#include <cuda_bf16.h>
#include <mma.h>
#include <math.h>
#include <cstdint>

using namespace nvcuda;

#define D_MODEL 1024
#define N_HEADS 16
#define HDIM    64
#define SEQ     2048
#define BATCH   2
#define TOKENS  (BATCH * SEQ)      // 4096
#define QKV_N   (3 * D_MODEL)      // 3072

// Scratch (device globals: allocation-free rule)
__device__ int    g_dtype;                       // 0=f32, 1=f16, 2=bf16
__device__ __half g_xh[TOKENS * D_MODEL];
__device__ __half g_owh[D_MODEL * D_MODEL];
__device__ __half g_wqkv[D_MODEL * QKV_N];
__device__ __half g_qkv[TOKENS * QKV_N];
__device__ __half g_merged[TOKENS * D_MODEL];

template <typename T> __device__ __forceinline__ T cvt_out(float x);
template <> __device__ __forceinline__ float  cvt_out<float>(float x)  { return x; }
template <> __device__ __forceinline__ __half cvt_out<__half>(float x) { return __float2half(x); }

__device__ __forceinline__ float load_as(const void* p, size_t i, int dt) {
    if (dt == 0) return ((const float*)p)[i];
    if (dt == 1) return __half2float(((const __half*)p)[i]);
    return __bfloat162float(((const __nv_bfloat16*)p)[i]);
}

// cp.async helpers (LDGSTS)
__device__ __forceinline__ void cp_async16(void* sptr, const void* gptr) {
    unsigned int sa = (unsigned int)__cvta_generic_to_shared(sptr);
    asm volatile("cp.async.cg.shared.global [%0], [%1], 16;\n" :: "r"(sa), "l"(gptr));
}
__device__ __forceinline__ void cp_commit() {
    asm volatile("cp.async.commit_group;\n" ::);
}
template <int N> __device__ __forceinline__ void cp_wait() {
    asm volatile("cp.async.wait_group %0;\n" :: "n"(N));
}

// ---------------------------------------------------------------------------
// Detect input dtype from x statistics (mean|x| ~= 0.798 for the true one).
// ---------------------------------------------------------------------------
__global__ void detect_dtype_kernel(const void* __restrict__ x) {
    __shared__ float red[3][256];
    int tid = threadIdx.x;
    float acc[3] = {0.f, 0.f, 0.f};
    for (int i = tid; i < 8192; i += 256) {
#pragma unroll
        for (int d = 0; d < 3; d++) {
            float v = fabsf(load_as(x, i, d));
            if (!isfinite(v)) v = 1e6f;
            acc[d] += fminf(v, 1e6f);
        }
    }
#pragma unroll
    for (int d = 0; d < 3; d++) red[d][tid] = acc[d];
    __syncthreads();
    for (int s = 128; s > 0; s >>= 1) {
        if (tid < s)
#pragma unroll
            for (int d = 0; d < 3; d++) red[d][tid] += red[d][tid + s];
        __syncthreads();
    }
    if (tid == 0) {
        int best = 0;
        float bestscore = 1e30f;
        for (int d = 0; d < 3; d++) {
            float mean = red[d][0] / 8192.0f;
            float score = fabsf(logf(mean + 1e-30f) - logf(0.798f));
            if (score < bestscore) { bestscore = score; best = d; }
        }
        g_dtype = best;
    }
}

__global__ void convert_kernel(const void* __restrict__ src,
                               __half* __restrict__ dst, int n) {
    int i = blockIdx.x * blockDim.x + threadIdx.x;
    if (i >= n) return;
    dst[i] = __float2half(load_as(src, i, g_dtype));
}

__global__ void pack_qkv_kernel(const void* __restrict__ qw,
                                const void* __restrict__ kw,
                                const void* __restrict__ vw,
                                __half* __restrict__ wp) {
    int i = blockIdx.x * blockDim.x + threadIdx.x;
    if (i >= D_MODEL * D_MODEL) return;
    int k = i >> 10;
    int c = i & 1023;
    int dt = g_dtype;
    __half* dst = wp + (size_t)k * QKV_N + c;
    dst[0]           = __float2half(load_as(qw, i, dt));
    dst[D_MODEL]     = __float2half(load_as(kw, i, dt));
    dst[2 * D_MODEL] = __float2half(load_as(vw, i, dt));
}

// ---------------------------------------------------------------------------
// wmma GEMM with 2-stage cp.async double buffering.
// C[MxN] = A[MxK] * B[KxN], fp16 in, fp32 accum. Tile 128x128x32, 8 warps.
// ---------------------------------------------------------------------------
template <typename OutT>
__global__ __launch_bounds__(256)
void gemm_f16_kernel(const __half* __restrict__ A,
                     const __half* __restrict__ B,
                     OutT* __restrict__ C,
                     int M, int N, int K) {
    constexpr int BM = 128, BN = 128, BK = 32;
    __shared__ __half sA[2][BM][BK + 8];   // 80B rows
    __shared__ __half sB[2][BK][BN + 8];   // 272B rows
    __shared__ float  sScr[8][256];

    int tid  = threadIdx.x;
    int warp = tid >> 5, lane = tid & 31;
    int wm = warp & 3;
    int wn = warp >> 2;
    int bm = blockIdx.y * BM;
    int bn = blockIdx.x * BN;
    int ntiles = K / BK;

    int ar0 = tid >> 1, ac0 = (tid & 1) * 2;
    int br0 = tid >> 3, bc0 = (tid & 7) * 2;

    auto issue_tile = [&](int k0, int st) {
#pragma unroll
        for (int u = 0; u < 2; u++)
            cp_async16(&sA[st][ar0][(ac0 + u) * 8],
                       &A[(size_t)(bm + ar0) * K + k0 + (ac0 + u) * 8]);
#pragma unroll
        for (int u = 0; u < 2; u++)
            cp_async16(&sB[st][br0][(bc0 + u) * 8],
                       &B[(size_t)(k0 + br0) * N + bn + (bc0 + u) * 8]);
        cp_commit();
    };

    wmma::fragment<wmma::accumulator, 16, 16, 16, float> acc[2][4];
#pragma unroll
    for (int i = 0; i < 2; i++)
#pragma unroll
        for (int j = 0; j < 4; j++) wmma::fill_fragment(acc[i][j], 0.0f);

    issue_tile(0, 0);

    for (int t = 0; t < ntiles; t++) {
        int cur = t & 1;
        if (t + 1 < ntiles) {
            issue_tile((t + 1) * BK, (t + 1) & 1);
            cp_wait<1>();
        } else {
            cp_wait<0>();
        }
        __syncthreads();

#pragma unroll
        for (int kk = 0; kk < BK; kk += 16) {
            wmma::fragment<wmma::matrix_a, 16, 16, 16, half, wmma::row_major> af[2];
            wmma::fragment<wmma::matrix_b, 16, 16, 16, half, wmma::row_major> bf[4];
#pragma unroll
            for (int i = 0; i < 2; i++)
                wmma::load_matrix_sync(af[i], &sA[cur][wm * 32 + i * 16][kk], BK + 8);
#pragma unroll
            for (int j = 0; j < 4; j++)
                wmma::load_matrix_sync(bf[j], &sB[cur][kk][wn * 64 + j * 16], BN + 8);
#pragma unroll
            for (int i = 0; i < 2; i++)
#pragma unroll
                for (int j = 0; j < 4; j++)
                    wmma::mma_sync(acc[i][j], af[i], bf[j], acc[i][j]);
        }
        __syncthreads();
    }

#pragma unroll
    for (int i = 0; i < 2; i++) {
#pragma unroll
        for (int j = 0; j < 4; j++) {
            wmma::store_matrix_sync(&sScr[warp][0], acc[i][j], 16, wmma::mem_row_major);
            __syncwarp();
            int r0 = bm + wm * 32 + i * 16;
            int c0 = bn + wn * 64 + j * 16;
#pragma unroll
            for (int e = lane; e < 256; e += 32) {
                C[(size_t)(r0 + (e >> 4)) * N + c0 + (e & 15)] =
                    cvt_out<OutT>(sScr[warp][e]);
            }
            __syncwarp();
        }
    }
}

// ---------------------------------------------------------------------------
// RoPE in place on Q and K slices of g_qkv. Folds 1/32 score scale into Q.
// ---------------------------------------------------------------------------
__global__ void rope_kernel(__half* __restrict__ qkv) {
    int idx = blockIdx.x * blockDim.x + threadIdx.x;
    const int total = TOKENS * N_HEADS * (HDIM / 2);
    if (idx >= total) return;
    int i = idx & 31;
    int h = (idx >> 5) & 15;
    int t = idx >> 9;
    int s = t & (SEQ - 1);

    float inv = powf(10000.0f, -(float)i * (1.0f / 32.0f));
    float ang = (float)s * inv;
    float sn, cs;
    sincosf(ang, &sn, &cs);

    size_t base = (size_t)t * QKV_N + h * HDIM + 2 * i;
    float x1 = __half2float(qkv[base]);
    float x2 = __half2float(qkv[base + 1]);
    qkv[base]     = __float2half((x1 * cs - x2 * sn) * 0.03125f);
    qkv[base + 1] = __float2half((x1 * sn + x2 * cs) * 0.03125f);
    base += D_MODEL;
    x1 = __half2float(qkv[base]);
    x2 = __half2float(qkv[base + 1]);
    qkv[base]     = __float2half(x1 * cs - x2 * sn);
    qkv[base + 1] = __float2half(x1 * sn + x2 * cs);
}

// ---------------------------------------------------------------------------
// Flash attention v2: Q-tile 128 rows, 256 threads (8 warps x 16 rows),
// cp.async double-buffered K/V (64-key tiles), softmax 2 threads/row.
// ---------------------------------------------------------------------------
__global__ __launch_bounds__(256)
void attn_kernel(const __half* __restrict__ qkv, __half* __restrict__ merged) {
    extern __shared__ __align__(16) char smem_raw[];
    __half* sQP = (__half*)smem_raw;             // [128][72]: Q, then P
    __half* sK  = sQP + 128 * 72;                // [2][64][72]
    __half* sV  = sK + 2 * 64 * 72;              // [2][64][72]
    float*  sS  = (float*)(sV + 2 * 64 * 72);    // [128][72]: S, then Otmp
    float*  sO  = sS + 128 * 72;                 // [128][72]
    float*  m     = sO + 128 * 72;               // [128]
    float*  l     = m + 128;
    float*  alpha = l + 128;

    int qt = blockIdx.x;              // 0..15 (128-query tiles)
    int bh = blockIdx.y;              // 0..31
    int b = bh >> 4, h = bh & 15;
    const __half* Qg = qkv + (size_t)b * SEQ * QKV_N + h * HDIM;
    const __half* Kg = Qg + D_MODEL;
    const __half* Vg = Qg + 2 * D_MODEL;
    int tid = threadIdx.x, warp = tid >> 5;

    // load Q tile (128x64): 1024 uint4
    for (int i = tid; i < 1024; i += 256) {
        int r = i >> 3, cg = i & 7;
        *(uint4*)&sQP[r * 72 + cg * 8] =
            *(const uint4*)&Qg[(size_t)(qt * 128 + r) * QKV_N + cg * 8];
    }
    for (int i = tid; i < 128 * 72; i += 256) sO[i] = 0.0f;
    if (tid < 128) { m[tid] = -1e30f; l[tid] = 0.0f; }
    __syncthreads();

    // Q fragments persist in registers (warp w owns rows [16w,16w+16))
    wmma::fragment<wmma::matrix_a, 16, 16, 16, half, wmma::row_major> qf[4];
#pragma unroll
    for (int kk = 0; kk < 4; kk++)
        wmma::load_matrix_sync(qf[kk], &sQP[(warp * 16) * 72 + kk * 16], 72);
    __syncthreads();

    int kvmax = 2 * qt + 2;

    auto issue_kv = [&](int kv, int st) {
#pragma unroll
        for (int u = 0; u < 2; u++) {
            int i = tid + u * 256;         // 0..511
            int r = i >> 3, cg = i & 7;
            cp_async16(&sK[st * 64 * 72 + r * 72 + cg * 8],
                       &Kg[(size_t)(kv * 64 + r) * QKV_N + cg * 8]);
            cp_async16(&sV[st * 64 * 72 + r * 72 + cg * 8],
                       &Vg[(size_t)(kv * 64 + r) * QKV_N + cg * 8]);
        }
        cp_commit();
    };

    issue_kv(0, 0);

    for (int kv = 0; kv < kvmax; kv++) {
        int cur = kv & 1;
        if (kv + 1 < kvmax) { issue_kv(kv + 1, cur ^ 1); cp_wait<1>(); }
        else                { cp_wait<0>(); }
        __syncthreads();

        // S = Q @ K^T  (warp w: rows 16w..16w+15, all 64 key cols)
        wmma::fragment<wmma::accumulator, 16, 16, 16, float> sacc[4];
#pragma unroll
        for (int n = 0; n < 4; n++) wmma::fill_fragment(sacc[n], 0.0f);
#pragma unroll
        for (int kk = 0; kk < 4; kk++) {
#pragma unroll
            for (int n = 0; n < 4; n++) {
                wmma::fragment<wmma::matrix_b, 16, 16, 16, half, wmma::col_major> kf;
                wmma::load_matrix_sync(kf, &sK[cur * 64 * 72 + (n * 16) * 72 + kk * 16], 72);
                wmma::mma_sync(sacc[n], qf[kk], kf, sacc[n]);
            }
        }
#pragma unroll
        for (int n = 0; n < 4; n++)
            wmma::store_matrix_sync(&sS[(warp * 16) * 72 + n * 16], sacc[n],
                                    72, wmma::mem_row_major);
        __syncthreads();

        // online softmax: 2 threads per row, 32 cols each
        {
            int r  = tid >> 1;
            int hf = tid & 1;
            int qrow = qt * 128 + r;
            int lim = qrow - kv * 64 + 1;           // may be <=0 (fully masked)
            if (lim > 64) lim = 64;
            int c0 = hf * 32;
            int ce = c0 + 32 < lim ? c0 + 32 : lim;
            float mo = m[r];
            float tmax = -1e30f;
            for (int c = c0; c < ce; c++) tmax = fmaxf(tmax, sS[r * 72 + c]);
            tmax = fmaxf(tmax, __shfl_xor_sync(0xffffffffu, tmax, 1));
            float mnew = fmaxf(mo, tmax);
            float a = __expf(mo - mnew);
            float sum = 0.0f;
            for (int c = c0; c < c0 + 32; c++) {
                float p = (c < lim) ? __expf(sS[r * 72 + c] - mnew) : 0.0f;
                sum += p;
                sQP[r * 72 + c] = __float2half(p);
            }
            sum += __shfl_xor_sync(0xffffffffu, sum, 1);
            if (hf == 0) { m[r] = mnew; l[r] = l[r] * a + sum; alpha[r] = a; }
        }
        __syncthreads();

        // Otmp = P @ V  -> sS
        wmma::fragment<wmma::accumulator, 16, 16, 16, float> oacc[4];
#pragma unroll
        for (int n = 0; n < 4; n++) wmma::fill_fragment(oacc[n], 0.0f);
#pragma unroll
        for (int kk = 0; kk < 4; kk++) {
            wmma::fragment<wmma::matrix_a, 16, 16, 16, half, wmma::row_major> pf;
            wmma::load_matrix_sync(pf, &sQP[(warp * 16) * 72 + kk * 16], 72);
#pragma unroll
            for (int n = 0; n < 4; n++) {
                wmma::fragment<wmma::matrix_b, 16, 16, 16, half, wmma::row_major> vf;
                wmma::load_matrix_sync(vf, &sV[cur * 64 * 72 + (kk * 16) * 72 + n * 16], 72);
                wmma::mma_sync(oacc[n], pf, vf, oacc[n]);
            }
        }
#pragma unroll
        for (int n = 0; n < 4; n++)
            wmma::store_matrix_sync(&sS[(warp * 16) * 72 + n * 16], oacc[n],
                                    72, wmma::mem_row_major);
        __syncthreads();

        // O = O*alpha_row + Otmp
        for (int i = tid; i < 128 * 64; i += 256) {
            int rr = i >> 6, cc = i & 63;
            sO[rr * 72 + cc] = sO[rr * 72 + cc] * alpha[rr] + sS[rr * 72 + cc];
        }
        __syncthreads();
    }

    for (int i = tid; i < 128 * 64; i += 256) {
        int rr = i >> 6, cc = i & 63;
        merged[(size_t)(b * SEQ + qt * 128 + rr) * D_MODEL + h * HDIM + cc] =
            __float2half(sO[rr * 72 + cc] / l[rr]);
    }
}

// ---------------------------------------------------------------------------
// Launch
// ---------------------------------------------------------------------------
extern "C" void kernel_launch(void* const* d_in, const int* in_sizes, int n_in,
                              void* d_out, int out_size) {
    const void* x  = d_in[0];
    const void* qw = d_in[1];
    const void* kw = d_in[2];
    const void* vw = d_in[3];
    const void* ow = d_in[4];
    float* out = (float*)d_out;

    __half *xh, *owh, *wqkv, *qkvb, *mg;
    cudaGetSymbolAddress((void**)&xh,   g_xh);
    cudaGetSymbolAddress((void**)&owh,  g_owh);
    cudaGetSymbolAddress((void**)&wqkv, g_wqkv);
    cudaGetSymbolAddress((void**)&qkvb, g_qkv);
    cudaGetSymbolAddress((void**)&mg,   g_merged);

    detect_dtype_kernel<<<1, 256>>>(x);

    int nx = TOKENS * D_MODEL;
    int nw = D_MODEL * D_MODEL;
    convert_kernel<<<(nx + 255) / 256, 256>>>(x, xh, nx);
    convert_kernel<<<(nw + 255) / 256, 256>>>(ow, owh, nw);
    pack_qkv_kernel<<<(nw + 255) / 256, 256>>>(qw, kw, vw, wqkv);

    dim3 g1(QKV_N / 128, TOKENS / 128);
    gemm_f16_kernel<__half><<<g1, 256>>>(xh, wqkv, qkvb, TOKENS, QKV_N, D_MODEL);

    int rope_total = TOKENS * N_HEADS * (HDIM / 2);
    rope_kernel<<<(rope_total + 255) / 256, 256>>>(qkvb);

    // attention smem: QP(128*72*2) + K(2*64*72*2) + V(2*64*72*2)
    //               + S(128*72*4) + O(128*72*4) + 3*128*4 = 130560
    int attn_smem = 128 * 72 * 2 + 2 * (2 * 64 * 72 * 2) + 2 * (128 * 72 * 4) + 3 * 128 * 4;
    cudaFuncSetAttribute(attn_kernel,
                         cudaFuncAttributeMaxDynamicSharedMemorySize, attn_smem);
    dim3 g2(SEQ / 128, BATCH * N_HEADS);
    attn_kernel<<<g2, 256, attn_smem>>>(qkvb, mg);

    dim3 g3(D_MODEL / 128, TOKENS / 128);
    gemm_f16_kernel<float><<<g3, 256>>>(mg, owh, out, TOKENS, D_MODEL, D_MODEL);
}

// round 7
// speedup vs baseline: 6.8884x; 1.3519x over previous
#include <cuda_runtime.h>
#include <cuda_fp16.h>
#include <cuda_bf16.h>
#include <mma.h>
#include <math.h>
#include <cstdint>

using namespace nvcuda;

#define D_MODEL 1024
#define N_HEADS 16
#define HDIM    64
#define SEQ     2048
#define BATCH   2
#define TOKENS  (BATCH * SEQ)      // 4096
#define QKV_N   (3 * D_MODEL)      // 3072

// Scratch (device globals: allocation-free rule)
__device__ int    g_dtype;                       // 0=f32, 1=f16, 2=bf16
__device__ __half g_xh[TOKENS * D_MODEL];
__device__ __half g_owh[D_MODEL * D_MODEL];
__device__ __half g_wqkv[D_MODEL * QKV_N];
__device__ __half g_qkv[TOKENS * QKV_N];
__device__ __half g_merged[TOKENS * D_MODEL];

template <typename T> __device__ __forceinline__ T cvt_out(float x);
template <> __device__ __forceinline__ float  cvt_out<float>(float x)  { return x; }
template <> __device__ __forceinline__ __half cvt_out<__half>(float x) { return __float2half(x); }

__device__ __forceinline__ float load_as(const void* p, size_t i, int dt) {
    if (dt == 0) return ((const float*)p)[i];
    if (dt == 1) return __half2float(((const __half*)p)[i]);
    return __bfloat162float(((const __nv_bfloat16*)p)[i]);
}

// cp.async helpers (LDGSTS)
__device__ __forceinline__ void cp_async16(void* sptr, const void* gptr) {
    unsigned int sa = (unsigned int)__cvta_generic_to_shared(sptr);
    asm volatile("cp.async.cg.shared.global [%0], [%1], 16;\n" :: "r"(sa), "l"(gptr));
}
__device__ __forceinline__ void cp_commit() {
    asm volatile("cp.async.commit_group;\n" ::);
}
template <int N> __device__ __forceinline__ void cp_wait() {
    asm volatile("cp.async.wait_group %0;\n" :: "n"(N));
}

// ---------------------------------------------------------------------------
// Detect input dtype from x statistics (mean|x| ~= 0.798 for the true one).
// ---------------------------------------------------------------------------
__global__ void detect_dtype_kernel(const void* __restrict__ x) {
    __shared__ float red[3][256];
    int tid = threadIdx.x;
    float acc[3] = {0.f, 0.f, 0.f};
    for (int i = tid; i < 8192; i += 256) {
#pragma unroll
        for (int d = 0; d < 3; d++) {
            float v = fabsf(load_as(x, i, d));
            if (!isfinite(v)) v = 1e6f;
            acc[d] += fminf(v, 1e6f);
        }
    }
#pragma unroll
    for (int d = 0; d < 3; d++) red[d][tid] = acc[d];
    __syncthreads();
    for (int s = 128; s > 0; s >>= 1) {
        if (tid < s)
#pragma unroll
            for (int d = 0; d < 3; d++) red[d][tid] += red[d][tid + s];
        __syncthreads();
    }
    if (tid == 0) {
        int best = 0;
        float bestscore = 1e30f;
        for (int d = 0; d < 3; d++) {
            float mean = red[d][0] / 8192.0f;
            float score = fabsf(logf(mean + 1e-30f) - logf(0.798f));
            if (score < bestscore) { bestscore = score; best = d; }
        }
        g_dtype = best;
    }
}

__global__ void convert_kernel(const void* __restrict__ src,
                               __half* __restrict__ dst, int n) {
    int i = blockIdx.x * blockDim.x + threadIdx.x;
    if (i >= n) return;
    dst[i] = __float2half(load_as(src, i, g_dtype));
}

__global__ void pack_qkv_kernel(const void* __restrict__ qw,
                                const void* __restrict__ kw,
                                const void* __restrict__ vw,
                                __half* __restrict__ wp) {
    int i = blockIdx.x * blockDim.x + threadIdx.x;
    if (i >= D_MODEL * D_MODEL) return;
    int k = i >> 10;
    int c = i & 1023;
    int dt = g_dtype;
    __half* dst = wp + (size_t)k * QKV_N + c;
    dst[0]           = __float2half(load_as(qw, i, dt));
    dst[D_MODEL]     = __float2half(load_as(kw, i, dt));
    dst[2 * D_MODEL] = __float2half(load_as(vw, i, dt));
}

// ---------------------------------------------------------------------------
// wmma GEMM, 2-stage cp.async, block tile 256x128x32, warp tile 64x64.
// 8 warps (4 along M x 2 along N). Dynamic smem, epilogue reuses sA space.
// ---------------------------------------------------------------------------
template <typename OutT>
__global__ __launch_bounds__(256)
void gemm_f16_kernel(const __half* __restrict__ A,
                     const __half* __restrict__ B,
                     OutT* __restrict__ C,
                     int M, int N, int K) {
    constexpr int BM = 256, BN = 128, BK = 32;
    constexpr int APITCH = BK + 8;     // 40 halves (80B)
    constexpr int BPITCH = BN + 8;     // 136 halves (272B)
    extern __shared__ __align__(16) char gsm[];
    __half* sA = (__half*)gsm;                          // [2][BM][APITCH] 40960B
    __half* sB = sA + 2 * BM * APITCH;                  // [2][BK][BPITCH] 17408B
    float*  sScr = (float*)gsm;                         // epilogue reuse (8*256 fl)

    int tid  = threadIdx.x;
    int warp = tid >> 5, lane = tid & 31;
    int wm = warp & 3;                 // 0..3 along M (64 rows each)
    int wn = warp >> 2;                // 0..1 along N (64 cols each)
    int bm = blockIdx.y * BM;
    int bn = blockIdx.x * BN;
    int ntiles = K / BK;

    auto issue_tile = [&](int k0, int st) {
        __half* dA = sA + st * BM * APITCH;
        __half* dB = sB + st * BK * BPITCH;
#pragma unroll
        for (int u = 0; u < 4; u++) {                  // A: 1024 chunks
            int c = tid + u * 256;
            int r = c >> 2, cg = c & 3;
            cp_async16(&dA[r * APITCH + cg * 8],
                       &A[(size_t)(bm + r) * K + k0 + cg * 8]);
        }
#pragma unroll
        for (int u = 0; u < 2; u++) {                  // B: 512 chunks
            int c = tid + u * 256;
            int r = c >> 4, cg = c & 15;
            cp_async16(&dB[r * BPITCH + cg * 8],
                       &B[(size_t)(k0 + r) * N + bn + cg * 8]);
        }
        cp_commit();
    };

    wmma::fragment<wmma::accumulator, 16, 16, 16, float> acc[4][4];
#pragma unroll
    for (int i = 0; i < 4; i++)
#pragma unroll
        for (int j = 0; j < 4; j++) wmma::fill_fragment(acc[i][j], 0.0f);

    issue_tile(0, 0);

    for (int t = 0; t < ntiles; t++) {
        int cur = t & 1;
        if (t + 1 < ntiles) { issue_tile((t + 1) * BK, cur ^ 1); cp_wait<1>(); }
        else                { cp_wait<0>(); }
        __syncthreads();

        const __half* cA = sA + cur * BM * APITCH;
        const __half* cB = sB + cur * BK * BPITCH;
#pragma unroll
        for (int kk = 0; kk < BK; kk += 16) {
            wmma::fragment<wmma::matrix_a, 16, 16, 16, half, wmma::row_major> af[4];
            wmma::fragment<wmma::matrix_b, 16, 16, 16, half, wmma::row_major> bf[4];
#pragma unroll
            for (int i = 0; i < 4; i++)
                wmma::load_matrix_sync(af[i], &cA[(wm * 64 + i * 16) * APITCH + kk], APITCH);
#pragma unroll
            for (int j = 0; j < 4; j++)
                wmma::load_matrix_sync(bf[j], &cB[kk * BPITCH + wn * 64 + j * 16], BPITCH);
#pragma unroll
            for (int i = 0; i < 4; i++)
#pragma unroll
                for (int j = 0; j < 4; j++)
                    wmma::mma_sync(acc[i][j], af[i], bf[j], acc[i][j]);
        }
        __syncthreads();
    }

    // epilogue: per-warp smem scratch (reuses sA region; all tiles consumed)
#pragma unroll
    for (int i = 0; i < 4; i++) {
#pragma unroll
        for (int j = 0; j < 4; j++) {
            wmma::store_matrix_sync(&sScr[warp * 256], acc[i][j], 16, wmma::mem_row_major);
            __syncwarp();
            int r0 = bm + wm * 64 + i * 16;
            int c0 = bn + wn * 64 + j * 16;
#pragma unroll
            for (int e = lane; e < 256; e += 32) {
                C[(size_t)(r0 + (e >> 4)) * N + c0 + (e & 15)] =
                    cvt_out<OutT>(sScr[warp * 256 + e]);
            }
            __syncwarp();
        }
    }
}

// ---------------------------------------------------------------------------
// RoPE in place on Q and K slices of g_qkv. Folds 1/32 score scale into Q.
// ---------------------------------------------------------------------------
__global__ void rope_kernel(__half* __restrict__ qkv) {
    int idx = blockIdx.x * blockDim.x + threadIdx.x;
    const int total = TOKENS * N_HEADS * (HDIM / 2);
    if (idx >= total) return;
    int i = idx & 31;
    int h = (idx >> 5) & 15;
    int t = idx >> 9;
    int s = t & (SEQ - 1);

    float inv = powf(10000.0f, -(float)i * (1.0f / 32.0f));
    float ang = (float)s * inv;
    float sn, cs;
    sincosf(ang, &sn, &cs);

    size_t base = (size_t)t * QKV_N + h * HDIM + 2 * i;
    float x1 = __half2float(qkv[base]);
    float x2 = __half2float(qkv[base + 1]);
    qkv[base]     = __float2half((x1 * cs - x2 * sn) * 0.03125f);
    qkv[base + 1] = __float2half((x1 * sn + x2 * cs) * 0.03125f);
    base += D_MODEL;
    x1 = __half2float(qkv[base]);
    x2 = __half2float(qkv[base + 1]);
    qkv[base]     = __float2half(x1 * cs - x2 * sn);
    qkv[base + 1] = __float2half(x1 * sn + x2 * cs);
}

// ---------------------------------------------------------------------------
// Flash attention: Q-tile 128 rows, 256 threads (8 warps x 16 rows),
// cp.async double-buffered K/V, vectorized softmax (2 threads/row) and
// vectorized O update.
// ---------------------------------------------------------------------------
__global__ __launch_bounds__(256)
void attn_kernel(const __half* __restrict__ qkv, __half* __restrict__ merged) {
    extern __shared__ __align__(16) char smem_raw[];
    __half* sQP = (__half*)smem_raw;             // [128][72]: Q, then P
    __half* sK  = sQP + 128 * 72;                // [2][64][72]
    __half* sV  = sK + 2 * 64 * 72;              // [2][64][72]
    float*  sS  = (float*)(sV + 2 * 64 * 72);    // [128][72]: S, then Otmp
    float*  sO  = sS + 128 * 72;                 // [128][72]
    float*  m     = sO + 128 * 72;               // [128]
    float*  l     = m + 128;
    float*  alpha = l + 128;

    int qt = blockIdx.x;
    int bh = blockIdx.y;
    int b = bh >> 4, h = bh & 15;
    const __half* Qg = qkv + (size_t)b * SEQ * QKV_N + h * HDIM;
    const __half* Kg = Qg + D_MODEL;
    const __half* Vg = Qg + 2 * D_MODEL;
    int tid = threadIdx.x, warp = tid >> 5;

    for (int i = tid; i < 1024; i += 256) {
        int r = i >> 3, cg = i & 7;
        *(uint4*)&sQP[r * 72 + cg * 8] =
            *(const uint4*)&Qg[(size_t)(qt * 128 + r) * QKV_N + cg * 8];
    }
    for (int i = tid; i < 128 * 18; i += 256) ((float4*)sO)[i] = make_float4(0, 0, 0, 0);
    if (tid < 128) { m[tid] = -1e30f; l[tid] = 0.0f; }
    __syncthreads();

    wmma::fragment<wmma::matrix_a, 16, 16, 16, half, wmma::row_major> qf[4];
#pragma unroll
    for (int kk = 0; kk < 4; kk++)
        wmma::load_matrix_sync(qf[kk], &sQP[(warp * 16) * 72 + kk * 16], 72);
    __syncthreads();

    int kvmax = 2 * qt + 2;

    auto issue_kv = [&](int kv, int st) {
#pragma unroll
        for (int u = 0; u < 2; u++) {
            int i = tid + u * 256;
            int r = i >> 3, cg = i & 7;
            cp_async16(&sK[st * 64 * 72 + r * 72 + cg * 8],
                       &Kg[(size_t)(kv * 64 + r) * QKV_N + cg * 8]);
            cp_async16(&sV[st * 64 * 72 + r * 72 + cg * 8],
                       &Vg[(size_t)(kv * 64 + r) * QKV_N + cg * 8]);
        }
        cp_commit();
    };

    issue_kv(0, 0);

    for (int kv = 0; kv < kvmax; kv++) {
        int cur = kv & 1;
        if (kv + 1 < kvmax) { issue_kv(kv + 1, cur ^ 1); cp_wait<1>(); }
        else                { cp_wait<0>(); }
        __syncthreads();

        // S = Q @ K^T
        wmma::fragment<wmma::accumulator, 16, 16, 16, float> sacc[4];
#pragma unroll
        for (int n = 0; n < 4; n++) wmma::fill_fragment(sacc[n], 0.0f);
#pragma unroll
        for (int kk = 0; kk < 4; kk++) {
#pragma unroll
            for (int n = 0; n < 4; n++) {
                wmma::fragment<wmma::matrix_b, 16, 16, 16, half, wmma::col_major> kf;
                wmma::load_matrix_sync(kf, &sK[cur * 64 * 72 + (n * 16) * 72 + kk * 16], 72);
                wmma::mma_sync(sacc[n], qf[kk], kf, sacc[n]);
            }
        }
#pragma unroll
        for (int n = 0; n < 4; n++)
            wmma::store_matrix_sync(&sS[(warp * 16) * 72 + n * 16], sacc[n],
                                    72, wmma::mem_row_major);
        __syncthreads();

        // online softmax: 2 threads/row, 32 cols each, vectorized
        {
            int r  = tid >> 1;
            int hf = tid & 1;
            int qrow = qt * 128 + r;
            int lim = qrow - kv * 64 + 1;            // valid cols in [0,lim)
            if (lim > 64) lim = 64;
            int c0 = hf * 32;
            float mo = m[r];

            float4 sv[8];
            const float4* srow = (const float4*)&sS[r * 72 + c0];
#pragma unroll
            for (int u = 0; u < 8; u++) sv[u] = srow[u];

            float tmax = -1e30f;
#pragma unroll
            for (int u = 0; u < 8; u++) {
                int c = c0 + u * 4;
                if (c + 0 < lim) tmax = fmaxf(tmax, sv[u].x);
                if (c + 1 < lim) tmax = fmaxf(tmax, sv[u].y);
                if (c + 2 < lim) tmax = fmaxf(tmax, sv[u].z);
                if (c + 3 < lim) tmax = fmaxf(tmax, sv[u].w);
            }
            tmax = fmaxf(tmax, __shfl_xor_sync(0xffffffffu, tmax, 1));
            float mnew = fmaxf(mo, tmax);
            float a = __expf(mo - mnew);
            float sum = 0.0f;
            __half2* prow = (__half2*)&sQP[r * 72 + c0];
#pragma unroll
            for (int u = 0; u < 8; u++) {
                int c = c0 + u * 4;
                float p0 = (c + 0 < lim) ? __expf(sv[u].x - mnew) : 0.0f;
                float p1 = (c + 1 < lim) ? __expf(sv[u].y - mnew) : 0.0f;
                float p2 = (c + 2 < lim) ? __expf(sv[u].z - mnew) : 0.0f;
                float p3 = (c + 3 < lim) ? __expf(sv[u].w - mnew) : 0.0f;
                sum += (p0 + p1) + (p2 + p3);
                prow[u * 2 + 0] = __floats2half2_rn(p0, p1);
                prow[u * 2 + 1] = __floats2half2_rn(p2, p3);
            }
            sum += __shfl_xor_sync(0xffffffffu, sum, 1);
            if (hf == 0) { m[r] = mnew; l[r] = l[r] * a + sum; alpha[r] = a; }
        }
        __syncthreads();

        // Otmp = P @ V  -> sS
        wmma::fragment<wmma::accumulator, 16, 16, 16, float> oacc[4];
#pragma unroll
        for (int n = 0; n < 4; n++) wmma::fill_fragment(oacc[n], 0.0f);
#pragma unroll
        for (int kk = 0; kk < 4; kk++) {
            wmma::fragment<wmma::matrix_a, 16, 16, 16, half, wmma::row_major> pf;
            wmma::load_matrix_sync(pf, &sQP[(warp * 16) * 72 + kk * 16], 72);
#pragma unroll
            for (int n = 0; n < 4; n++) {
                wmma::fragment<wmma::matrix_b, 16, 16, 16, half, wmma::row_major> vf;
                wmma::load_matrix_sync(vf, &sV[cur * 64 * 72 + (kk * 16) * 72 + n * 16], 72);
                wmma::mma_sync(oacc[n], pf, vf, oacc[n]);
            }
        }
#pragma unroll
        for (int n = 0; n < 4; n++)
            wmma::store_matrix_sync(&sS[(warp * 16) * 72 + n * 16], oacc[n],
                                    72, wmma::mem_row_major);
        __syncthreads();

        // O = O*alpha_row + Otmp (vectorized: 2048 float4 ops)
        for (int i = tid; i < 2048; i += 256) {
            int rr = i >> 4, cq = i & 15;
            float av = alpha[rr];
            float4 ov = *(float4*)&sO[rr * 72 + cq * 4];
            float4 tv = *(float4*)&sS[rr * 72 + cq * 4];
            ov.x = ov.x * av + tv.x;
            ov.y = ov.y * av + tv.y;
            ov.z = ov.z * av + tv.z;
            ov.w = ov.w * av + tv.w;
            *(float4*)&sO[rr * 72 + cq * 4] = ov;
        }
        __syncthreads();
    }

    // normalize + store (vectorized half2 x4)
    for (int i = tid; i < 2048; i += 256) {
        int rr = i >> 4, cq = i & 15;
        float invl = 1.0f / l[rr];
        float4 ov = *(float4*)&sO[rr * 72 + cq * 4];
        __half2 h0 = __floats2half2_rn(ov.x * invl, ov.y * invl);
        __half2 h1 = __floats2half2_rn(ov.z * invl, ov.w * invl);
        __half2* dst = (__half2*)&merged[(size_t)(b * SEQ + qt * 128 + rr) * D_MODEL
                                         + h * HDIM + cq * 4];
        dst[0] = h0;
        dst[1] = h1;
    }
}

// ---------------------------------------------------------------------------
// Launch
// ---------------------------------------------------------------------------
extern "C" void kernel_launch(void* const* d_in, const int* in_sizes, int n_in,
                              void* d_out, int out_size) {
    const void* x  = d_in[0];
    const void* qw = d_in[1];
    const void* kw = d_in[2];
    const void* vw = d_in[3];
    const void* ow = d_in[4];
    float* out = (float*)d_out;

    __half *xh, *owh, *wqkv, *qkvb, *mg;
    cudaGetSymbolAddress((void**)&xh,   g_xh);
    cudaGetSymbolAddress((void**)&owh,  g_owh);
    cudaGetSymbolAddress((void**)&wqkv, g_wqkv);
    cudaGetSymbolAddress((void**)&qkvb, g_qkv);
    cudaGetSymbolAddress((void**)&mg,   g_merged);

    int nx = TOKENS * D_MODEL;
    int nw = D_MODEL * D_MODEL;

    // GEMM dynamic smem: sA 2*256*40*2 + sB 2*32*136*2 = 58368
    int gemm_smem = 2 * 256 * 40 * 2 + 2 * 32 * 136 * 2;
    cudaFuncSetAttribute(gemm_f16_kernel<__half>,
                         cudaFuncAttributeMaxDynamicSharedMemorySize, gemm_smem);
    cudaFuncSetAttribute(gemm_f16_kernel<float>,
                         cudaFuncAttributeMaxDynamicSharedMemorySize, gemm_smem);

    detect_dtype_kernel<<<1, 256>>>(x);
    convert_kernel<<<(nx + 255) / 256, 256>>>(x, xh, nx);
    pack_qkv_kernel<<<(nw + 255) / 256, 256>>>(qw, kw, vw, wqkv);

    // QKV projection: [4096x1024] @ [1024x3072]
    dim3 g1(QKV_N / 128, TOKENS / 256);
    gemm_f16_kernel<__half><<<g1, 256, gemm_smem>>>(xh, wqkv, qkvb,
                                                    TOKENS, QKV_N, D_MODEL);

    int rope_total = TOKENS * N_HEADS * (HDIM / 2);
    rope_kernel<<<(rope_total + 255) / 256, 256>>>(qkvb);

    int attn_smem = 128 * 72 * 2 + 2 * (2 * 64 * 72 * 2) + 2 * (128 * 72 * 4) + 3 * 128 * 4;
    cudaFuncSetAttribute(attn_kernel,
                         cudaFuncAttributeMaxDynamicSharedMemorySize, attn_smem);
    dim3 g2(SEQ / 128, BATCH * N_HEADS);
    attn_kernel<<<g2, 256, attn_smem>>>(qkvb, mg);

    convert_kernel<<<(nw + 255) / 256, 256>>>(ow, owh, nw);

    // output projection: [4096x1024] @ [1024x1024] -> fp32
    dim3 g3(D_MODEL / 128, TOKENS / 256);
    gemm_f16_kernel<float><<<g3, 256, gemm_smem>>>(mg, owh, out,
                                                   TOKENS, D_MODEL, D_MODEL);
}

// round 8
// speedup vs baseline: 7.6425x; 1.1095x over previous
#include <cuda_runtime.h>
#include <cuda_fp16.h>
#include <cuda_bf16.h>
#include <mma.h>
#include <math.h>
#include <cstdint>

using namespace nvcuda;

#define D_MODEL 1024
#define N_HEADS 16
#define HDIM    64
#define SEQ     2048
#define BATCH   2
#define TOKENS  (BATCH * SEQ)      // 4096
#define QKV_N   (3 * D_MODEL)      // 3072

// Scratch (device globals: allocation-free rule)
__device__ int    g_dtype;                       // 0=f32, 1=f16, 2=bf16
__device__ __half g_xh[TOKENS * D_MODEL];
__device__ __half g_owh[D_MODEL * D_MODEL];
__device__ __half g_wqkv[D_MODEL * QKV_N];
__device__ __half g_qkv[TOKENS * QKV_N];
__device__ __half g_merged[TOKENS * D_MODEL];

template <typename T> __device__ __forceinline__ T cvt_out(float x);
template <> __device__ __forceinline__ float  cvt_out<float>(float x)  { return x; }
template <> __device__ __forceinline__ __half cvt_out<__half>(float x) { return __float2half(x); }

__device__ __forceinline__ float load_as(const void* p, size_t i, int dt) {
    if (dt == 0) return ((const float*)p)[i];
    if (dt == 1) return __half2float(((const __half*)p)[i]);
    return __bfloat162float(((const __nv_bfloat16*)p)[i]);
}

// cp.async helpers (LDGSTS)
__device__ __forceinline__ void cp_async16(void* sptr, const void* gptr) {
    unsigned int sa = (unsigned int)__cvta_generic_to_shared(sptr);
    asm volatile("cp.async.cg.shared.global [%0], [%1], 16;\n" :: "r"(sa), "l"(gptr));
}
__device__ __forceinline__ void cp_commit() {
    asm volatile("cp.async.commit_group;\n" ::);
}
template <int N> __device__ __forceinline__ void cp_wait() {
    asm volatile("cp.async.wait_group %0;\n" :: "n"(N));
}

// ---------------------------------------------------------------------------
// Detect input dtype from x statistics (mean|x| ~= 0.798 for the true one).
// ---------------------------------------------------------------------------
__global__ void detect_dtype_kernel(const void* __restrict__ x) {
    __shared__ float red[3][256];
    int tid = threadIdx.x;
    float acc[3] = {0.f, 0.f, 0.f};
    for (int i = tid; i < 8192; i += 256) {
#pragma unroll
        for (int d = 0; d < 3; d++) {
            float v = fabsf(load_as(x, i, d));
            if (!isfinite(v)) v = 1e6f;
            acc[d] += fminf(v, 1e6f);
        }
    }
#pragma unroll
    for (int d = 0; d < 3; d++) red[d][tid] = acc[d];
    __syncthreads();
    for (int s = 128; s > 0; s >>= 1) {
        if (tid < s)
#pragma unroll
            for (int d = 0; d < 3; d++) red[d][tid] += red[d][tid + s];
        __syncthreads();
    }
    if (tid == 0) {
        int best = 0;
        float bestscore = 1e30f;
        for (int d = 0; d < 3; d++) {
            float mean = red[d][0] / 8192.0f;
            float score = fabsf(logf(mean + 1e-30f) - logf(0.798f));
            if (score < bestscore) { bestscore = score; best = d; }
        }
        g_dtype = best;
    }
}

__global__ void convert_kernel(const void* __restrict__ src,
                               __half* __restrict__ dst, int n) {
    int i = blockIdx.x * blockDim.x + threadIdx.x;
    if (i >= n) return;
    dst[i] = __float2half(load_as(src, i, g_dtype));
}

__global__ void pack_qkv_kernel(const void* __restrict__ qw,
                                const void* __restrict__ kw,
                                const void* __restrict__ vw,
                                __half* __restrict__ wp) {
    int i = blockIdx.x * blockDim.x + threadIdx.x;
    if (i >= D_MODEL * D_MODEL) return;
    int k = i >> 10;
    int c = i & 1023;
    int dt = g_dtype;
    __half* dst = wp + (size_t)k * QKV_N + c;
    dst[0]           = __float2half(load_as(qw, i, dt));
    dst[D_MODEL]     = __float2half(load_as(kw, i, dt));
    dst[2 * D_MODEL] = __float2half(load_as(vw, i, dt));
}

// ---------------------------------------------------------------------------
// wmma GEMM, 2-stage cp.async, block tile 256x128x32, warp tile 64x64.
// ---------------------------------------------------------------------------
template <typename OutT>
__global__ __launch_bounds__(256)
void gemm_f16_kernel(const __half* __restrict__ A,
                     const __half* __restrict__ B,
                     OutT* __restrict__ C,
                     int M, int N, int K) {
    constexpr int BM = 256, BN = 128, BK = 32;
    constexpr int APITCH = BK + 8;
    constexpr int BPITCH = BN + 8;
    extern __shared__ __align__(16) char gsm[];
    __half* sA = (__half*)gsm;
    __half* sB = sA + 2 * BM * APITCH;
    float*  sScr = (float*)gsm;

    int tid  = threadIdx.x;
    int warp = tid >> 5, lane = tid & 31;
    int wm = warp & 3;
    int wn = warp >> 2;
    int bm = blockIdx.y * BM;
    int bn = blockIdx.x * BN;
    int ntiles = K / BK;

    auto issue_tile = [&](int k0, int st) {
        __half* dA = sA + st * BM * APITCH;
        __half* dB = sB + st * BK * BPITCH;
#pragma unroll
        for (int u = 0; u < 4; u++) {
            int c = tid + u * 256;
            int r = c >> 2, cg = c & 3;
            cp_async16(&dA[r * APITCH + cg * 8],
                       &A[(size_t)(bm + r) * K + k0 + cg * 8]);
        }
#pragma unroll
        for (int u = 0; u < 2; u++) {
            int c = tid + u * 256;
            int r = c >> 4, cg = c & 15;
            cp_async16(&dB[r * BPITCH + cg * 8],
                       &B[(size_t)(k0 + r) * N + bn + cg * 8]);
        }
        cp_commit();
    };

    wmma::fragment<wmma::accumulator, 16, 16, 16, float> acc[4][4];
#pragma unroll
    for (int i = 0; i < 4; i++)
#pragma unroll
        for (int j = 0; j < 4; j++) wmma::fill_fragment(acc[i][j], 0.0f);

    issue_tile(0, 0);

    for (int t = 0; t < ntiles; t++) {
        int cur = t & 1;
        if (t + 1 < ntiles) { issue_tile((t + 1) * BK, cur ^ 1); cp_wait<1>(); }
        else                { cp_wait<0>(); }
        __syncthreads();

        const __half* cA = sA + cur * BM * APITCH;
        const __half* cB = sB + cur * BK * BPITCH;
#pragma unroll
        for (int kk = 0; kk < BK; kk += 16) {
            wmma::fragment<wmma::matrix_a, 16, 16, 16, half, wmma::row_major> af[4];
            wmma::fragment<wmma::matrix_b, 16, 16, 16, half, wmma::row_major> bf[4];
#pragma unroll
            for (int i = 0; i < 4; i++)
                wmma::load_matrix_sync(af[i], &cA[(wm * 64 + i * 16) * APITCH + kk], APITCH);
#pragma unroll
            for (int j = 0; j < 4; j++)
                wmma::load_matrix_sync(bf[j], &cB[kk * BPITCH + wn * 64 + j * 16], BPITCH);
#pragma unroll
            for (int i = 0; i < 4; i++)
#pragma unroll
                for (int j = 0; j < 4; j++)
                    wmma::mma_sync(acc[i][j], af[i], bf[j], acc[i][j]);
        }
        __syncthreads();
    }

#pragma unroll
    for (int i = 0; i < 4; i++) {
#pragma unroll
        for (int j = 0; j < 4; j++) {
            wmma::store_matrix_sync(&sScr[warp * 256], acc[i][j], 16, wmma::mem_row_major);
            __syncwarp();
            int r0 = bm + wm * 64 + i * 16;
            int c0 = bn + wn * 64 + j * 16;
#pragma unroll
            for (int e = lane; e < 256; e += 32) {
                C[(size_t)(r0 + (e >> 4)) * N + c0 + (e & 15)] =
                    cvt_out<OutT>(sScr[warp * 256 + e]);
            }
            __syncwarp();
        }
    }
}

// ---------------------------------------------------------------------------
// RoPE in place on Q and K slices of g_qkv. Folds 1/32 score scale into Q.
// ---------------------------------------------------------------------------
__global__ void rope_kernel(__half* __restrict__ qkv) {
    int idx = blockIdx.x * blockDim.x + threadIdx.x;
    const int total = TOKENS * N_HEADS * (HDIM / 2);
    if (idx >= total) return;
    int i = idx & 31;
    int h = (idx >> 5) & 15;
    int t = idx >> 9;
    int s = t & (SEQ - 1);

    float inv = powf(10000.0f, -(float)i * (1.0f / 32.0f));
    float ang = (float)s * inv;
    float sn, cs;
    sincosf(ang, &sn, &cs);

    size_t base = (size_t)t * QKV_N + h * HDIM + 2 * i;
    float x1 = __half2float(qkv[base]);
    float x2 = __half2float(qkv[base + 1]);
    qkv[base]     = __float2half((x1 * cs - x2 * sn) * 0.03125f);
    qkv[base + 1] = __float2half((x1 * sn + x2 * cs) * 0.03125f);
    base += D_MODEL;
    x1 = __half2float(qkv[base]);
    x2 = __half2float(qkv[base + 1]);
    qkv[base]     = __float2half(x1 * cs - x2 * sn);
    qkv[base + 1] = __float2half(x1 * sn + x2 * cs);
}

// ---------------------------------------------------------------------------
// Flash attention v3 — warp-local softmax & register O accumulator.
// Q-tile 128 rows, 256 threads (8 warps). Warp w owns rows [16w, 16w+16):
// its S/P/O rows touch only its own smem rows, so per-iteration ordering is
// __syncwarp; block syncs only guard the shared K/V double buffers (2/iter).
// Lane mapping: row = 16w + (lane>>1), col-half = 32*(lane&1).
// Softmax state (m, l) and O (32 floats) live in registers.
// ---------------------------------------------------------------------------
__global__ __launch_bounds__(256)
void attn_kernel(const __half* __restrict__ qkv, __half* __restrict__ merged) {
    extern __shared__ __align__(16) char smem_raw[];
    __half* sQP = (__half*)smem_raw;             // [128][72]: Q, then P
    __half* sK  = sQP + 128 * 72;                // [2][64][72]
    __half* sV  = sK + 2 * 64 * 72;              // [2][64][72]
    float*  sS  = (float*)(sV + 2 * 64 * 72);    // [128][72]: S, then Otmp

    int qt = blockIdx.x;
    int bh = blockIdx.y;
    int b = bh >> 4, h = bh & 15;
    const __half* Qg = qkv + (size_t)b * SEQ * QKV_N + h * HDIM;
    const __half* Kg = Qg + D_MODEL;
    const __half* Vg = Qg + 2 * D_MODEL;
    int tid = threadIdx.x, warp = tid >> 5, lane = tid & 31;
    int rloc = warp * 16 + (lane >> 1);          // row this lane co-owns
    int c0   = (lane & 1) * 32;                  // col half

    // load Q tile (128x64)
    for (int i = tid; i < 1024; i += 256) {
        int r = i >> 3, cg = i & 7;
        *(uint4*)&sQP[r * 72 + cg * 8] =
            *(const uint4*)&Qg[(size_t)(qt * 128 + r) * QKV_N + cg * 8];
    }
    __syncthreads();

    // Q fragments persist in registers. (Warp w reads only rows 16w..16w+15,
    // the same rows it later overwrites with P — no cross-warp hazard.)
    wmma::fragment<wmma::matrix_a, 16, 16, 16, half, wmma::row_major> qf[4];
#pragma unroll
    for (int kk = 0; kk < 4; kk++)
        wmma::load_matrix_sync(qf[kk], &sQP[(warp * 16) * 72 + kk * 16], 72);

    float mrun = -1e30f, lrun = 0.0f;
    float Oacc[32];
#pragma unroll
    for (int u = 0; u < 32; u++) Oacc[u] = 0.0f;

    int kvmax = 2 * qt + 2;

    auto issue_kv = [&](int kv, int st) {
#pragma unroll
        for (int u = 0; u < 2; u++) {
            int i = tid + u * 256;
            int r = i >> 3, cg = i & 7;
            cp_async16(&sK[st * 64 * 72 + r * 72 + cg * 8],
                       &Kg[(size_t)(kv * 64 + r) * QKV_N + cg * 8]);
            cp_async16(&sV[st * 64 * 72 + r * 72 + cg * 8],
                       &Vg[(size_t)(kv * 64 + r) * QKV_N + cg * 8]);
        }
        cp_commit();
    };

    issue_kv(0, 0);

    for (int kv = 0; kv < kvmax; kv++) {
        int cur = kv & 1;
        __syncthreads();   // all warps done reading buffer cur^1 (iter kv-1)
        if (kv + 1 < kvmax) { issue_kv(kv + 1, cur ^ 1); cp_wait<1>(); }
        else                { cp_wait<0>(); }
        __syncthreads();   // buffer cur visible to all warps

        // skip fully-masked warp tiles (top-right of the diagonal tile)
        if (qt * 128 + warp * 16 + 15 < kv * 64) continue;

        // S = Q @ K^T  (warp-local rows)
        wmma::fragment<wmma::accumulator, 16, 16, 16, float> sacc[4];
#pragma unroll
        for (int n = 0; n < 4; n++) wmma::fill_fragment(sacc[n], 0.0f);
#pragma unroll
        for (int kk = 0; kk < 4; kk++) {
#pragma unroll
            for (int n = 0; n < 4; n++) {
                wmma::fragment<wmma::matrix_b, 16, 16, 16, half, wmma::col_major> kf;
                wmma::load_matrix_sync(kf, &sK[cur * 64 * 72 + (n * 16) * 72 + kk * 16], 72);
                wmma::mma_sync(sacc[n], qf[kk], kf, sacc[n]);
            }
        }
#pragma unroll
        for (int n = 0; n < 4; n++)
            wmma::store_matrix_sync(&sS[(warp * 16) * 72 + n * 16], sacc[n],
                                    72, wmma::mem_row_major);
        __syncwarp();

        // warp-local online softmax (2 lanes per row, 32 cols each)
        {
            int qrow = qt * 128 + rloc;
            int lim = qrow - kv * 64 + 1;         // valid cols in [0,lim)
            if (lim > 64) lim = 64;

            float4 sv[8];
            const float4* srow = (const float4*)&sS[rloc * 72 + c0];
#pragma unroll
            for (int u = 0; u < 8; u++) sv[u] = srow[u];

            float tmax = -1e30f;
#pragma unroll
            for (int u = 0; u < 8; u++) {
                int c = c0 + u * 4;
                if (c + 0 < lim) tmax = fmaxf(tmax, sv[u].x);
                if (c + 1 < lim) tmax = fmaxf(tmax, sv[u].y);
                if (c + 2 < lim) tmax = fmaxf(tmax, sv[u].z);
                if (c + 3 < lim) tmax = fmaxf(tmax, sv[u].w);
            }
            tmax = fmaxf(tmax, __shfl_xor_sync(0xffffffffu, tmax, 1));
            float mnew = fmaxf(mrun, tmax);
            float a = __expf(mrun - mnew);
            mrun = mnew;

            float sum = 0.0f;
            __half2* prow = (__half2*)&sQP[rloc * 72 + c0];
#pragma unroll
            for (int u = 0; u < 8; u++) {
                int c = c0 + u * 4;
                float p0 = (c + 0 < lim) ? __expf(sv[u].x - mnew) : 0.0f;
                float p1 = (c + 1 < lim) ? __expf(sv[u].y - mnew) : 0.0f;
                float p2 = (c + 2 < lim) ? __expf(sv[u].z - mnew) : 0.0f;
                float p3 = (c + 3 < lim) ? __expf(sv[u].w - mnew) : 0.0f;
                sum += (p0 + p1) + (p2 + p3);
                prow[u * 2 + 0] = __floats2half2_rn(p0, p1);
                prow[u * 2 + 1] = __floats2half2_rn(p2, p3);
            }
            sum += __shfl_xor_sync(0xffffffffu, sum, 1);
            lrun = lrun * a + sum;

            __syncwarp();

            // Otmp = P @ V -> sS (warp-local rows)
            wmma::fragment<wmma::accumulator, 16, 16, 16, float> oacc[4];
#pragma unroll
            for (int n = 0; n < 4; n++) wmma::fill_fragment(oacc[n], 0.0f);
#pragma unroll
            for (int kk = 0; kk < 4; kk++) {
                wmma::fragment<wmma::matrix_a, 16, 16, 16, half, wmma::row_major> pf;
                wmma::load_matrix_sync(pf, &sQP[(warp * 16) * 72 + kk * 16], 72);
#pragma unroll
                for (int n = 0; n < 4; n++) {
                    wmma::fragment<wmma::matrix_b, 16, 16, 16, half, wmma::row_major> vf;
                    wmma::load_matrix_sync(vf, &sV[cur * 64 * 72 + (kk * 16) * 72 + n * 16], 72);
                    wmma::mma_sync(oacc[n], pf, vf, oacc[n]);
                }
            }
#pragma unroll
            for (int n = 0; n < 4; n++)
                wmma::store_matrix_sync(&sS[(warp * 16) * 72 + n * 16], oacc[n],
                                        72, wmma::mem_row_major);
            __syncwarp();

            // O = O*a + Otmp (registers; lane reads its own 32 cols)
            const float4* orow = (const float4*)&sS[rloc * 72 + c0];
#pragma unroll
            for (int u = 0; u < 8; u++) {
                float4 tv = orow[u];
                Oacc[u * 4 + 0] = Oacc[u * 4 + 0] * a + tv.x;
                Oacc[u * 4 + 1] = Oacc[u * 4 + 1] * a + tv.y;
                Oacc[u * 4 + 2] = Oacc[u * 4 + 2] * a + tv.z;
                Oacc[u * 4 + 3] = Oacc[u * 4 + 3] * a + tv.w;
            }
            __syncwarp();   // sS reads done before next iteration's QK store
        }
    }

    // normalize + store (each (row, col) written exactly once)
    float invl = 1.0f / lrun;
    __half2* dst = (__half2*)&merged[(size_t)(b * SEQ + qt * 128 + rloc) * D_MODEL
                                     + h * HDIM + c0];
#pragma unroll
    for (int u = 0; u < 16; u++)
        dst[u] = __floats2half2_rn(Oacc[u * 2] * invl, Oacc[u * 2 + 1] * invl);
}

// ---------------------------------------------------------------------------
// Launch
// ---------------------------------------------------------------------------
extern "C" void kernel_launch(void* const* d_in, const int* in_sizes, int n_in,
                              void* d_out, int out_size) {
    const void* x  = d_in[0];
    const void* qw = d_in[1];
    const void* kw = d_in[2];
    const void* vw = d_in[3];
    const void* ow = d_in[4];
    float* out = (float*)d_out;

    __half *xh, *owh, *wqkv, *qkvb, *mg;
    cudaGetSymbolAddress((void**)&xh,   g_xh);
    cudaGetSymbolAddress((void**)&owh,  g_owh);
    cudaGetSymbolAddress((void**)&wqkv, g_wqkv);
    cudaGetSymbolAddress((void**)&qkvb, g_qkv);
    cudaGetSymbolAddress((void**)&mg,   g_merged);

    int nx = TOKENS * D_MODEL;
    int nw = D_MODEL * D_MODEL;

    int gemm_smem = 2 * 256 * 40 * 2 + 2 * 32 * 136 * 2;   // 58368
    cudaFuncSetAttribute(gemm_f16_kernel<__half>,
                         cudaFuncAttributeMaxDynamicSharedMemorySize, gemm_smem);
    cudaFuncSetAttribute(gemm_f16_kernel<float>,
                         cudaFuncAttributeMaxDynamicSharedMemorySize, gemm_smem);

    detect_dtype_kernel<<<1, 256>>>(x);
    convert_kernel<<<(nx + 255) / 256, 256>>>(x, xh, nx);
    pack_qkv_kernel<<<(nw + 255) / 256, 256>>>(qw, kw, vw, wqkv);

    dim3 g1(QKV_N / 128, TOKENS / 256);
    gemm_f16_kernel<__half><<<g1, 256, gemm_smem>>>(xh, wqkv, qkvb,
                                                    TOKENS, QKV_N, D_MODEL);

    int rope_total = TOKENS * N_HEADS * (HDIM / 2);
    rope_kernel<<<(rope_total + 255) / 256, 256>>>(qkvb);

    // attn smem: QP 128*72*2 + K/V 2*(2*64*72*2) + S 128*72*4 = 92160
    int attn_smem = 128 * 72 * 2 + 2 * (2 * 64 * 72 * 2) + 128 * 72 * 4;
    cudaFuncSetAttribute(attn_kernel,
                         cudaFuncAttributeMaxDynamicSharedMemorySize, attn_smem);
    dim3 g2(SEQ / 128, BATCH * N_HEADS);
    attn_kernel<<<g2, 256, attn_smem>>>(qkvb, mg);

    convert_kernel<<<(nw + 255) / 256, 256>>>(ow, owh, nw);

    dim3 g3(D_MODEL / 128, TOKENS / 256);
    gemm_f16_kernel<float><<<g3, 256, gemm_smem>>>(mg, owh, out,
                                                   TOKENS, D_MODEL, D_MODEL);
}